// round 8
// baseline (speedup 1.0000x reference)
#include <cuda_runtime.h>
#include <cstdint>

#define BB 256
#define TT 256
#define DD 64
#define HH 256
#define GG 768

// ---------------- scratch ----------------
__device__ float g_XT[TT * BB * DD];
__device__ float g_H1[TT * BB * 2 * HH];
__device__ float g_GI[2 * TT * BB * GG];

// ---------------- helpers ----------------
__device__ __forceinline__ float sigmoidf_fast(float x) {
    return 1.0f / (1.0f + __expf(-x));
}
__device__ __forceinline__ unsigned cvt_tf32(float f) {
    unsigned r;
    asm volatile("cvt.rna.tf32.f32 %0, %1;" : "=r"(r) : "f"(f));
    return r;
}
__device__ __forceinline__ unsigned mapa_sh(unsigned addr, unsigned rnk) {
    unsigned ra;
    asm volatile("mapa.shared::cluster.u32 %0, %1, %2;" : "=r"(ra) : "r"(addr), "r"(rnk));
    return ra;
}
#define CLUSTER_SYNC_() \
    asm volatile("barrier.cluster.arrive.aligned;\n\tbarrier.cluster.wait.aligned;" ::: "memory")

__device__ __forceinline__ void mma_tf32(float* acc, const unsigned* a, unsigned b0, unsigned b1) {
    asm volatile(
        "mma.sync.aligned.m16n8k8.row.col.f32.tf32.tf32.f32 "
        "{%0,%1,%2,%3}, {%4,%5,%6,%7}, {%8,%9}, {%0,%1,%2,%3};\n"
        : "+f"(acc[0]), "+f"(acc[1]), "+f"(acc[2]), "+f"(acc[3])
        : "r"(a[0]), "r"(a[1]), "r"(a[2]), "r"(a[3]), "r"(b0), "r"(b1));
}

// ---------------- transpose x: (B,T,D) -> (T,B,D) ----------------
__global__ void transpose_x(const float* __restrict__ x) {
    int i = blockIdx.x * blockDim.x + threadIdx.x;
    if (i >= BB * TT * (DD / 4)) return;
    int d4 = i & 15;
    int t  = (i >> 4) & 255;
    int b  = i >> 12;
    const float4* src = reinterpret_cast<const float4*>(x);
    float4* dst = reinterpret_cast<float4*>(g_XT);
    dst[((t * BB + b) * (DD / 4)) + d4] = src[((b * TT + t) * (DD / 4)) + d4];
}

__global__ void dummy_k() {}   // launch-order shim: scan0 at ncu -s 5

// ---------------- gi GEMM: tf32x3, 128x128 tiles (validated, unchanged) ----------------
#define Bb_M 128
#define Bb_N 128
#define Bb_K 16
#define SSTR 20

__global__ void __launch_bounds__(256) gemm_tf32(int layer,
                                                 const float* __restrict__ Wih,
                                                 const float* __restrict__ bih,
                                                 const float* __restrict__ bhh) {
    __shared__ float sA[2][Bb_M * SSTR];
    __shared__ float sB[2][Bb_N * SSTR];

    const float* A = layer ? g_H1 : g_XT;
    const int K    = layer ? 512 : 64;
    float* C = g_GI;

    int tid  = threadIdx.x;
    int m0   = blockIdx.x * Bb_M;
    int n0   = blockIdx.y * Bb_N;
    int d    = blockIdx.z;
    const float* Ab = A + (size_t)m0 * K;
    const float* Wb = Wih + ((size_t)d * GG + n0) * K;
    float* Cb = C + (size_t)d * (TT * BB) * GG;

    int lane = tid & 31, wid = tid >> 5;
    int wm = wid & 3, wn = wid >> 2;

    float acc[2][8][4];
#pragma unroll
    for (int a = 0; a < 2; a++)
#pragma unroll
        for (int b = 0; b < 8; b++)
#pragma unroll
            for (int c = 0; c < 4; c++) acc[a][b][c] = 0.0f;

    auto load_tile = [&](int kt, int buf) {
        int k0 = kt * Bb_K;
#pragma unroll
        for (int i = 0; i < 2; i++) {
            int s   = tid * 2 + i;
            int row = s >> 2;
            int seg = s & 3;
            unsigned da = (unsigned)__cvta_generic_to_shared(&sA[buf][row * SSTR + seg * 4]);
            const float* ga = Ab + (size_t)row * K + k0 + seg * 4;
            asm volatile("cp.async.cg.shared.global [%0], [%1], 16;\n" :: "r"(da), "l"(ga));
            unsigned db = (unsigned)__cvta_generic_to_shared(&sB[buf][row * SSTR + seg * 4]);
            const float* gb = Wb + (size_t)row * K + k0 + seg * 4;
            asm volatile("cp.async.cg.shared.global [%0], [%1], 16;\n" :: "r"(db), "l"(gb));
        }
        asm volatile("cp.async.commit_group;\n" ::: "memory");
    };

    const int KT = K / Bb_K;
    load_tile(0, 0);
    for (int kt = 0; kt < KT; kt++) {
        int buf = kt & 1;
        if (kt + 1 < KT) {
            load_tile(kt + 1, buf ^ 1);
            asm volatile("cp.async.wait_group 1;\n" ::: "memory");
        } else {
            asm volatile("cp.async.wait_group 0;\n" ::: "memory");
        }
        __syncthreads();
        const float* a_s = sA[buf];
        const float* b_s = sB[buf];
#pragma unroll
        for (int ks = 0; ks < 2; ks++) {
            int kk = ks * 8;
            unsigned ahi[2][4], alo[2][4];
#pragma unroll
            for (int mf = 0; mf < 2; mf++) {
                const float* p = a_s + (wm * 32 + mf * 16 + (lane >> 2)) * SSTR + kk + (lane & 3);
                float f0 = p[0];
                float f1 = p[8 * SSTR];
                float f2 = p[4];
                float f3 = p[8 * SSTR + 4];
                ahi[mf][0] = cvt_tf32(f0); alo[mf][0] = __float_as_uint(f0 - __uint_as_float(ahi[mf][0]));
                ahi[mf][1] = cvt_tf32(f1); alo[mf][1] = __float_as_uint(f1 - __uint_as_float(ahi[mf][1]));
                ahi[mf][2] = cvt_tf32(f2); alo[mf][2] = __float_as_uint(f2 - __uint_as_float(ahi[mf][2]));
                ahi[mf][3] = cvt_tf32(f3); alo[mf][3] = __float_as_uint(f3 - __uint_as_float(ahi[mf][3]));
            }
#pragma unroll
            for (int nf = 0; nf < 8; nf++) {
                const float* p = b_s + (wn * 64 + nf * 8 + (lane >> 2)) * SSTR + kk + (lane & 3);
                float g0 = p[0];
                float g1 = p[4];
                unsigned bhi0 = cvt_tf32(g0), blo0 = __float_as_uint(g0 - __uint_as_float(bhi0));
                unsigned bhi1 = cvt_tf32(g1), blo1 = __float_as_uint(g1 - __uint_as_float(bhi1));
#pragma unroll
                for (int mf = 0; mf < 2; mf++) {
                    mma_tf32(acc[mf][nf], ahi[mf], bhi0, bhi1);
                    mma_tf32(acc[mf][nf], ahi[mf], blo0, blo1);
                    mma_tf32(acc[mf][nf], alo[mf], bhi0, bhi1);
                }
            }
        }
        __syncthreads();
    }

#pragma unroll
    for (int mf = 0; mf < 2; mf++)
#pragma unroll
        for (int nf = 0; nf < 8; nf++)
#pragma unroll
            for (int i = 0; i < 4; i++) {
                int row = m0 + wm * 32 + mf * 16 + (lane >> 2) + ((i >> 1) ? 8 : 0);
                int col = n0 + wn * 64 + nf * 8 + (lane & 3) * 2 + (i & 1);
                float bias = __ldg(&bih[d * GG + col]) +
                             (col < 2 * HH ? __ldg(&bhh[d * GG + col]) : 0.0f);
                Cb[(size_t)row * GG + col] = acc[mf][nf][i] + bias;
            }
}

// ---------------- GRU scan v4: mma recurrence + staged epilogue ----------------
// Cluster of 4 CTAs = (dir, 16-batch chunk). CTA rank owns j-slice [rank*64, +64):
// 192 gate rows. W loaded DIRECTLY from w_hh (no prep). Per step:
//   phase1: h(16x256) @ W(192x256)^T via m16n8k8 tf32x3; accs -> staging smem using
//           the gemm's exact epilogue (row,col) formula.
//   phase2: thread (b, 4 consecutive jl) gates from staging + gi + hold, broadcasts
//           h_new to all 4 CTAs' h buffers via st.shared::cluster.
#define WPAD 260
#define WSTG 68
#define W_SM_BYTES (192 * WPAD * 4)                        // 199680
#define H_SM_BYTES (16 * WPAD * 4)                         // 16640
#define S_SM_BYTES (3 * 16 * WSTG * 4)                     // 13056
#define SMEM_SCAN  (W_SM_BYTES + H_SM_BYTES + S_SM_BYTES)  // 229376

__global__ void __launch_bounds__(256, 1) __cluster_dims__(4, 1, 1)
gru_scan_mma(int layer, const float* __restrict__ whh,
             const float* __restrict__ bhh, float* __restrict__ fin) {
    extern __shared__ char smem[];
    float* Wsm = reinterpret_cast<float*>(smem);                              // [192][WPAD]
    float* hsm = reinterpret_cast<float*>(smem + W_SM_BYTES);                 // [16][WPAD]
    float* stg = reinterpret_cast<float*>(smem + W_SM_BYTES + H_SM_BYTES);    // [3][16][WSTG]

    int tid  = threadIdx.x;
    int lane = tid & 31;
    int w    = tid >> 5;
    int rank = blockIdx.x & 3;
    int cid  = blockIdx.x >> 2;
    int d    = cid & 1;
    int b0   = (cid >> 1) * 16;

    // W slice straight from w_hh: Wsm[n][k], n = g*64+jl <- w_hh[d][g*256 + rank*64 + jl][k]
    for (int i = tid; i < 192 * 64; i += 256) {
        int n = i >> 6, k4 = i & 63;
        int g = n >> 6, jl = n & 63;
        const float4* src = reinterpret_cast<const float4*>(
            whh + (size_t)(d * GG + g * 256 + rank * 64 + jl) * HH) + k4;
        *reinterpret_cast<float4*>(&Wsm[n * WPAD + k4 * 4]) = *src;
    }
    for (int i = tid; i < 16 * WPAD; i += 256) hsm[i] = 0.0f;

    // phase-2 ownership: thread -> (batch pb, 4 consecutive jl)
    int pb  = tid >> 4;          // 0..15
    int jl4 = (tid & 15) * 4;    // 0..60
    int jg4 = rank * 64 + jl4;
    float4 bn4 = *reinterpret_cast<const float4*>(&bhh[d * GG + 2 * HH + jg4]);

    CLUSTER_SYNC_();

    unsigned hlocal = (unsigned)__cvta_generic_to_shared(hsm);
    unsigned ha0 = mapa_sh(hlocal, 0);
    unsigned ha1 = mapa_sh(hlocal, 1);
    unsigned ha2 = mapa_sh(hlocal, 2);
    unsigned ha3 = mapa_sh(hlocal, 3);

    int ar = lane >> 2, ac = lane & 3;
    int nfr = 0 * 64 + w * 8;
    int nfz = 1 * 64 + w * 8;
    int nfn = 2 * 64 + w * 8;

    float hn0 = 0.f, hn1 = 0.f, hn2 = 0.f, hn3 = 0.f;

    for (int s = 0; s < TT; s++) {
        int t = d ? (TT - 1 - s) : s;

        // ---- phase 1: mma ----
        float accR[4] = {0.f, 0.f, 0.f, 0.f};
        float accZ[4] = {0.f, 0.f, 0.f, 0.f};
        float accN[4] = {0.f, 0.f, 0.f, 0.f};

#pragma unroll 4
        for (int kf = 0; kf < 32; kf++) {
            int k0 = kf * 8;
            float f0 = hsm[ar * WPAD + k0 + ac];
            float f1 = hsm[(ar + 8) * WPAD + k0 + ac];
            float f2 = hsm[ar * WPAD + k0 + ac + 4];
            float f3 = hsm[(ar + 8) * WPAD + k0 + ac + 4];
            unsigned ahi[4], alo[4];
            ahi[0] = cvt_tf32(f0); alo[0] = __float_as_uint(f0 - __uint_as_float(ahi[0]));
            ahi[1] = cvt_tf32(f1); alo[1] = __float_as_uint(f1 - __uint_as_float(ahi[1]));
            ahi[2] = cvt_tf32(f2); alo[2] = __float_as_uint(f2 - __uint_as_float(ahi[2]));
            ahi[3] = cvt_tf32(f3); alo[3] = __float_as_uint(f3 - __uint_as_float(ahi[3]));

            {
                const float* bp = &Wsm[(nfr + (lane >> 2)) * WPAD + k0 + (lane & 3)];
                float g0 = bp[0], g1 = bp[4];
                unsigned bh0 = cvt_tf32(g0), bl0 = __float_as_uint(g0 - __uint_as_float(bh0));
                unsigned bh1 = cvt_tf32(g1), bl1 = __float_as_uint(g1 - __uint_as_float(bh1));
                mma_tf32(accR, ahi, bh0, bh1);
                mma_tf32(accR, ahi, bl0, bl1);
                mma_tf32(accR, alo, bh0, bh1);
            }
            {
                const float* bp = &Wsm[(nfz + (lane >> 2)) * WPAD + k0 + (lane & 3)];
                float g0 = bp[0], g1 = bp[4];
                unsigned bh0 = cvt_tf32(g0), bl0 = __float_as_uint(g0 - __uint_as_float(bh0));
                unsigned bh1 = cvt_tf32(g1), bl1 = __float_as_uint(g1 - __uint_as_float(bh1));
                mma_tf32(accZ, ahi, bh0, bh1);
                mma_tf32(accZ, ahi, bl0, bl1);
                mma_tf32(accZ, alo, bh0, bh1);
            }
            {
                const float* bp = &Wsm[(nfn + (lane >> 2)) * WPAD + k0 + (lane & 3)];
                float g0 = bp[0], g1 = bp[4];
                unsigned bh0 = cvt_tf32(g0), bl0 = __float_as_uint(g0 - __uint_as_float(bh0));
                unsigned bh1 = cvt_tf32(g1), bl1 = __float_as_uint(g1 - __uint_as_float(bh1));
                mma_tf32(accN, ahi, bh0, bh1);
                mma_tf32(accN, ahi, bl0, bl1);
                mma_tf32(accN, alo, bh0, bh1);
            }
        }

        // stage accs via the gemm's validated epilogue (row,col) formula
#pragma unroll
        for (int i = 0; i < 4; i++) {
            int row = ar + ((i >> 1) ? 8 : 0);
            int col = w * 8 + (lane & 3) * 2 + (i & 1);
            stg[(0 * 16 + row) * WSTG + col] = accR[i];
            stg[(1 * 16 + row) * WSTG + col] = accZ[i];
            stg[(2 * 16 + row) * WSTG + col] = accN[i];
        }
        __syncthreads();

        // ---- phase 2: gating (thread owns (pb, jl4..jl4+3)) ----
        const float* gib = g_GI + ((size_t)d * (TT * BB) + (size_t)t * BB + b0 + pb) * GG;
        float4 gir = *reinterpret_cast<const float4*>(gib + jg4);
        float4 giz = *reinterpret_cast<const float4*>(gib + 256 + jg4);
        float4 gin = *reinterpret_cast<const float4*>(gib + 512 + jg4);
        float4 sR  = *reinterpret_cast<const float4*>(&stg[(0 * 16 + pb) * WSTG + jl4]);
        float4 sZ  = *reinterpret_cast<const float4*>(&stg[(1 * 16 + pb) * WSTG + jl4]);
        float4 sN  = *reinterpret_cast<const float4*>(&stg[(2 * 16 + pb) * WSTG + jl4]);
        float4 hO  = *reinterpret_cast<const float4*>(&hsm[pb * WPAD + jg4]);

        {
            float r, z, n;
            r = sigmoidf_fast(gir.x + sR.x);
            z = sigmoidf_fast(giz.x + sZ.x);
            n = tanhf(gin.x + r * (sN.x + bn4.x));
            hn0 = n + z * (hO.x - n);
            r = sigmoidf_fast(gir.y + sR.y);
            z = sigmoidf_fast(giz.y + sZ.y);
            n = tanhf(gin.y + r * (sN.y + bn4.y));
            hn1 = n + z * (hO.y - n);
            r = sigmoidf_fast(gir.z + sR.z);
            z = sigmoidf_fast(giz.z + sZ.z);
            n = tanhf(gin.z + r * (sN.z + bn4.z));
            hn2 = n + z * (hO.z - n);
            r = sigmoidf_fast(gir.w + sR.w);
            z = sigmoidf_fast(giz.w + sZ.w);
            n = tanhf(gin.w + r * (sN.w + bn4.w));
            hn3 = n + z * (hO.w - n);
        }

        CLUSTER_SYNC_();   // all cluster reads of hsm done

        unsigned off = (unsigned)(pb * WPAD + jg4) * 4u;
        asm volatile("st.shared::cluster.f32 [%0], %1;" :: "r"(ha0 + off),      "f"(hn0) : "memory");
        asm volatile("st.shared::cluster.f32 [%0], %1;" :: "r"(ha0 + off + 4),  "f"(hn1) : "memory");
        asm volatile("st.shared::cluster.f32 [%0], %1;" :: "r"(ha0 + off + 8),  "f"(hn2) : "memory");
        asm volatile("st.shared::cluster.f32 [%0], %1;" :: "r"(ha0 + off + 12), "f"(hn3) : "memory");
        asm volatile("st.shared::cluster.f32 [%0], %1;" :: "r"(ha1 + off),      "f"(hn0) : "memory");
        asm volatile("st.shared::cluster.f32 [%0], %1;" :: "r"(ha1 + off + 4),  "f"(hn1) : "memory");
        asm volatile("st.shared::cluster.f32 [%0], %1;" :: "r"(ha1 + off + 8),  "f"(hn2) : "memory");
        asm volatile("st.shared::cluster.f32 [%0], %1;" :: "r"(ha1 + off + 12), "f"(hn3) : "memory");
        asm volatile("st.shared::cluster.f32 [%0], %1;" :: "r"(ha2 + off),      "f"(hn0) : "memory");
        asm volatile("st.shared::cluster.f32 [%0], %1;" :: "r"(ha2 + off + 4),  "f"(hn1) : "memory");
        asm volatile("st.shared::cluster.f32 [%0], %1;" :: "r"(ha2 + off + 8),  "f"(hn2) : "memory");
        asm volatile("st.shared::cluster.f32 [%0], %1;" :: "r"(ha2 + off + 12), "f"(hn3) : "memory");
        asm volatile("st.shared::cluster.f32 [%0], %1;" :: "r"(ha3 + off),      "f"(hn0) : "memory");
        asm volatile("st.shared::cluster.f32 [%0], %1;" :: "r"(ha3 + off + 4),  "f"(hn1) : "memory");
        asm volatile("st.shared::cluster.f32 [%0], %1;" :: "r"(ha3 + off + 8),  "f"(hn2) : "memory");
        asm volatile("st.shared::cluster.f32 [%0], %1;" :: "r"(ha3 + off + 12), "f"(hn3) : "memory");

        if (layer == 0) {
            float4 v4 = make_float4(hn0, hn1, hn2, hn3);
            *reinterpret_cast<float4*>(
                &g_H1[((size_t)t * BB + b0 + pb) * (2 * HH) + (size_t)d * HH + jg4]) = v4;
        }

        CLUSTER_SYNC_();   // h_new visible everywhere
    }

    if (layer != 0) {
        float4 v4 = make_float4(hn0, hn1, hn2, hn3);
        *reinterpret_cast<float4*>(
            &fin[(size_t)(b0 + pb) * (2 * HH) + (size_t)d * HH + jg4]) = v4;
    }
}

// ---------------- launch ----------------
extern "C" void kernel_launch(void* const* d_in, const int* in_sizes, int n_in,
                              void* d_out, int out_size) {
    (void)in_sizes; (void)n_in; (void)out_size;
    const float* x     = (const float*)d_in[0];
    const float* w_ih0 = (const float*)d_in[1];
    const float* w_hh0 = (const float*)d_in[2];
    const float* b_ih0 = (const float*)d_in[3];
    const float* b_hh0 = (const float*)d_in[4];
    const float* w_ih1 = (const float*)d_in[5];
    const float* w_hh1 = (const float*)d_in[6];
    const float* b_ih1 = (const float*)d_in[7];
    const float* b_hh1 = (const float*)d_in[8];
    float* out = (float*)d_out;

    cudaFuncSetAttribute(gru_scan_mma, cudaFuncAttributeMaxDynamicSharedMemorySize, SMEM_SCAN);

    // order (harness prepends 2): transpose=2, dummy=3, gemm0=4, scan0=5 <- ncu -s 5
    transpose_x<<<(BB * TT * (DD / 4) + 255) / 256, 256>>>(x);
    dummy_k<<<1, 1>>>();

    dim3 gg(512, 6, 2);
    gemm_tf32<<<gg, 256>>>(0, w_ih0, b_ih0, b_hh0);
    gru_scan_mma<<<128, 256, SMEM_SCAN>>>(0, w_hh0, b_hh0, nullptr);
    gemm_tf32<<<gg, 256>>>(1, w_ih1, b_ih1, b_hh1);
    gru_scan_mma<<<128, 256, SMEM_SCAN>>>(1, w_hh1, b_hh1, out);
}

// round 9
// speedup vs baseline: 1.5493x; 1.5493x over previous
#include <cuda_runtime.h>
#include <cuda_bf16.h>
#include <cstdint>

#define BB 256
#define TT 256
#define DD 64
#define HH 256
#define GG 768

// ---------------- scratch ----------------
__device__ float    g_XT[TT * BB * DD];
__device__ float    g_H1[TT * BB * 2 * HH];
__device__ float    g_GI[2 * TT * BB * GG];
__device__ unsigned g_Whi[16 * 24576];   // [l*2+d][rank] -> 24576 frag-ordered bf16x2 words (hi)
__device__ unsigned g_Wlo[16 * 24576];   // (lo)

// ---------------- helpers ----------------
__device__ __forceinline__ float sigmoidf_fast(float x) {
    return 1.0f / (1.0f + __expf(-x));
}
__device__ __forceinline__ unsigned cvt_tf32(float f) {
    unsigned r;
    asm volatile("cvt.rna.tf32.f32 %0, %1;" : "=r"(r) : "f"(f));
    return r;
}
__device__ __forceinline__ unsigned mapa_sh(unsigned addr, unsigned rnk) {
    unsigned ra;
    asm volatile("mapa.shared::cluster.u32 %0, %1, %2;" : "=r"(ra) : "r"(addr), "r"(rnk));
    return ra;
}
#define CLUSTER_SYNC_() \
    asm volatile("barrier.cluster.arrive.aligned;\n\tbarrier.cluster.wait.aligned;" ::: "memory")

__device__ __forceinline__ void mma_tf32(float* acc, const unsigned* a, unsigned b0, unsigned b1) {
    asm volatile(
        "mma.sync.aligned.m16n8k8.row.col.f32.tf32.tf32.f32 "
        "{%0,%1,%2,%3}, {%4,%5,%6,%7}, {%8,%9}, {%0,%1,%2,%3};\n"
        : "+f"(acc[0]), "+f"(acc[1]), "+f"(acc[2]), "+f"(acc[3])
        : "r"(a[0]), "r"(a[1]), "r"(a[2]), "r"(a[3]), "r"(b0), "r"(b1));
}
__device__ __forceinline__ void mma_bf16(float* acc, const unsigned* a, unsigned b0, unsigned b1) {
    asm volatile(
        "mma.sync.aligned.m16n8k16.row.col.f32.bf16.bf16.f32 "
        "{%0,%1,%2,%3}, {%4,%5,%6,%7}, {%8,%9}, {%0,%1,%2,%3};\n"
        : "+f"(acc[0]), "+f"(acc[1]), "+f"(acc[2]), "+f"(acc[3])
        : "r"(a[0]), "r"(a[1]), "r"(a[2]), "r"(a[3]), "r"(b0), "r"(b1));
}

// ---------------- transpose x ----------------
__global__ void transpose_x(const float* __restrict__ x) {
    int i = blockIdx.x * blockDim.x + threadIdx.x;
    if (i >= BB * TT * (DD / 4)) return;
    int d4 = i & 15;
    int t  = (i >> 4) & 255;
    int b  = i >> 12;
    const float4* src = reinterpret_cast<const float4*>(x);
    float4* dst = reinterpret_cast<float4*>(g_XT);
    dst[((t * BB + b) * (DD / 4)) + d4] = src[((b * TT + t) * (DD / 4)) + d4];
}

// ---------------- prep: split w_hh into fragment-ordered bf16 hi/lo planes ----------------
// word index: [(l*2+d)*4+rank][gf = g*8+f][kf][w64 = lane*2 + r]
//   row = g*256 + rank*64 + f*8 + (lane>>2);  k = kf*16 + (lane&3)*2 + r*8  (pair k, k+1)
__global__ void prep_wsplit(const float* __restrict__ w0, const float* __restrict__ w1) {
    int i = blockIdx.x * blockDim.x + threadIdx.x;
    if (i >= 16 * 24576) return;
    int w64  = i & 63;
    int blk  = i >> 6;
    int kf   = blk & 15;
    int gfid = blk >> 4;          // 0..383 per 16*(24)
    int gf   = gfid % 24;
    int ldr  = gfid / 24;         // (l*2+d)*4 + rank
    int rank = ldr & 3;
    int d    = (ldr >> 2) & 1;
    int l    = ldr >> 3;
    int g    = gf >> 3;
    int f    = gf & 7;
    int lane = w64 >> 1;
    int r    = w64 & 1;
    int row  = g * 256 + rank * 64 + f * 8 + (lane >> 2);
    int k    = kf * 16 + (lane & 3) * 2 + r * 8;
    const float* w = l ? w1 : w0;
    const float* p = w + ((size_t)d * GG + row) * HH + k;
    float v0 = p[0], v1 = p[1];
    __nv_bfloat16 h0 = __float2bfloat16(v0);
    __nv_bfloat16 h1 = __float2bfloat16(v1);
    __nv_bfloat16 l0 = __float2bfloat16(v0 - __bfloat162float(h0));
    __nv_bfloat16 l1 = __float2bfloat16(v1 - __bfloat162float(h1));
    g_Whi[i] = ((unsigned)__bfloat16_as_ushort(h1) << 16) | __bfloat16_as_ushort(h0);
    g_Wlo[i] = ((unsigned)__bfloat16_as_ushort(l1) << 16) | __bfloat16_as_ushort(l0);
}

// ---------------- gi GEMM: tf32x3, 128x128 tiles (validated, unchanged) ----------------
#define Bb_M 128
#define Bb_N 128
#define Bb_K 16
#define SSTR 20

__global__ void __launch_bounds__(256) gemm_tf32(int layer,
                                                 const float* __restrict__ Wih,
                                                 const float* __restrict__ bih,
                                                 const float* __restrict__ bhh) {
    __shared__ float sA[2][Bb_M * SSTR];
    __shared__ float sB[2][Bb_N * SSTR];

    const float* A = layer ? g_H1 : g_XT;
    const int K    = layer ? 512 : 64;
    float* C = g_GI;

    int tid  = threadIdx.x;
    int m0   = blockIdx.x * Bb_M;
    int n0   = blockIdx.y * Bb_N;
    int d    = blockIdx.z;
    const float* Ab = A + (size_t)m0 * K;
    const float* Wb = Wih + ((size_t)d * GG + n0) * K;
    float* Cb = C + (size_t)d * (TT * BB) * GG;

    int lane = tid & 31, wid = tid >> 5;
    int wm = wid & 3, wn = wid >> 2;

    float acc[2][8][4];
#pragma unroll
    for (int a = 0; a < 2; a++)
#pragma unroll
        for (int b = 0; b < 8; b++)
#pragma unroll
            for (int c = 0; c < 4; c++) acc[a][b][c] = 0.0f;

    auto load_tile = [&](int kt, int buf) {
        int k0 = kt * Bb_K;
#pragma unroll
        for (int i = 0; i < 2; i++) {
            int s   = tid * 2 + i;
            int row = s >> 2;
            int seg = s & 3;
            unsigned da = (unsigned)__cvta_generic_to_shared(&sA[buf][row * SSTR + seg * 4]);
            const float* ga = Ab + (size_t)row * K + k0 + seg * 4;
            asm volatile("cp.async.cg.shared.global [%0], [%1], 16;\n" :: "r"(da), "l"(ga));
            unsigned db = (unsigned)__cvta_generic_to_shared(&sB[buf][row * SSTR + seg * 4]);
            const float* gb = Wb + (size_t)row * K + k0 + seg * 4;
            asm volatile("cp.async.cg.shared.global [%0], [%1], 16;\n" :: "r"(db), "l"(gb));
        }
        asm volatile("cp.async.commit_group;\n" ::: "memory");
    };

    const int KT = K / Bb_K;
    load_tile(0, 0);
    for (int kt = 0; kt < KT; kt++) {
        int buf = kt & 1;
        if (kt + 1 < KT) {
            load_tile(kt + 1, buf ^ 1);
            asm volatile("cp.async.wait_group 1;\n" ::: "memory");
        } else {
            asm volatile("cp.async.wait_group 0;\n" ::: "memory");
        }
        __syncthreads();
        const float* a_s = sA[buf];
        const float* b_s = sB[buf];
#pragma unroll
        for (int ks = 0; ks < 2; ks++) {
            int kk = ks * 8;
            unsigned ahi[2][4], alo[2][4];
#pragma unroll
            for (int mf = 0; mf < 2; mf++) {
                const float* p = a_s + (wm * 32 + mf * 16 + (lane >> 2)) * SSTR + kk + (lane & 3);
                float f0 = p[0];
                float f1 = p[8 * SSTR];
                float f2 = p[4];
                float f3 = p[8 * SSTR + 4];
                ahi[mf][0] = cvt_tf32(f0); alo[mf][0] = __float_as_uint(f0 - __uint_as_float(ahi[mf][0]));
                ahi[mf][1] = cvt_tf32(f1); alo[mf][1] = __float_as_uint(f1 - __uint_as_float(ahi[mf][1]));
                ahi[mf][2] = cvt_tf32(f2); alo[mf][2] = __float_as_uint(f2 - __uint_as_float(ahi[mf][2]));
                ahi[mf][3] = cvt_tf32(f3); alo[mf][3] = __float_as_uint(f3 - __uint_as_float(ahi[mf][3]));
            }
#pragma unroll
            for (int nf = 0; nf < 8; nf++) {
                const float* p = b_s + (wn * 64 + nf * 8 + (lane >> 2)) * SSTR + kk + (lane & 3);
                float g0 = p[0];
                float g1 = p[4];
                unsigned bhi0 = cvt_tf32(g0), blo0 = __float_as_uint(g0 - __uint_as_float(bhi0));
                unsigned bhi1 = cvt_tf32(g1), blo1 = __float_as_uint(g1 - __uint_as_float(bhi1));
#pragma unroll
                for (int mf = 0; mf < 2; mf++) {
                    mma_tf32(acc[mf][nf], ahi[mf], bhi0, bhi1);
                    mma_tf32(acc[mf][nf], ahi[mf], blo0, blo1);
                    mma_tf32(acc[mf][nf], alo[mf], bhi0, bhi1);
                }
            }
        }
        __syncthreads();
    }

#pragma unroll
    for (int mf = 0; mf < 2; mf++)
#pragma unroll
        for (int nf = 0; nf < 8; nf++)
#pragma unroll
            for (int i = 0; i < 4; i++) {
                int row = m0 + wm * 32 + mf * 16 + (lane >> 2) + ((i >> 1) ? 8 : 0);
                int col = n0 + wn * 64 + nf * 8 + (lane & 3) * 2 + (i & 1);
                float bias = __ldg(&bih[d * GG + col]) +
                             (col < 2 * HH ? __ldg(&bhh[d * GG + col]) : 0.0f);
                Cb[(size_t)row * GG + col] = acc[mf][nf][i] + bias;
            }
}

// ---------------- GRU scan v5: bf16x2 pre-split mma recurrence ----------------
// 4-CTA cluster = (dir, 16-batch chunk); rank owns 64 j (192 gate rows).
// W in smem as fragment-ordered bf16x2 hi/lo planes (LDS.64 per B frag, no cvt).
// h in smem as padded bf16 hi/lo planes [16][264] (132 words/row, conflict-free A loads).
// hold = thread's own register. Staged epilogue identical to validated v4.
#define WPL_W   24576                      // words per W plane per CTA
#define APL_W   (16 * 132)                 // 2112 words per h plane
#define WH_OFF  0
#define WL_OFF  (WPL_W * 4)                // 98304
#define AHI_OFF (2 * WPL_W * 4)            // 196608
#define ALO_OFF (AHI_OFF + APL_W * 4)      // 205056
#define STG_OFF (ALO_OFF + APL_W * 4)      // 213504
#define WSTG 68
#define SMEM_SCAN (STG_OFF + 3 * 16 * WSTG * 4)   // 226560

__global__ void __launch_bounds__(256, 1) __cluster_dims__(4, 1, 1)
gru_scan_mma(int layer, const float* __restrict__ bhh, float* __restrict__ fin) {
    extern __shared__ char smem[];
    unsigned* Wh  = reinterpret_cast<unsigned*>(smem + WH_OFF);
    unsigned* Wl  = reinterpret_cast<unsigned*>(smem + WL_OFF);
    unsigned* hhi = reinterpret_cast<unsigned*>(smem + AHI_OFF);
    unsigned* hlo = reinterpret_cast<unsigned*>(smem + ALO_OFF);
    float*    stg = reinterpret_cast<float*>(smem + STG_OFF);

    int tid  = threadIdx.x;
    int lane = tid & 31;
    int w    = tid >> 5;
    int rank = blockIdx.x & 3;
    int cid  = blockIdx.x >> 2;
    int d    = cid & 1;
    int b0   = (cid >> 1) * 16;

    // load W planes (uint4 sweeps)
    {
        const uint4* shi = reinterpret_cast<const uint4*>(g_Whi + (size_t)((layer * 2 + d) * 4 + rank) * WPL_W);
        const uint4* slo = reinterpret_cast<const uint4*>(g_Wlo + (size_t)((layer * 2 + d) * 4 + rank) * WPL_W);
        uint4* dhi = reinterpret_cast<uint4*>(Wh);
        uint4* dlo = reinterpret_cast<uint4*>(Wl);
#pragma unroll 4
        for (int i = tid; i < WPL_W / 4; i += 256) { dhi[i] = shi[i]; dlo[i] = slo[i]; }
    }
    for (int i = tid; i < APL_W; i += 256) { hhi[i] = 0u; hlo[i] = 0u; }

    int pb  = tid >> 4;
    int jl4 = (tid & 15) * 4;
    int jg4 = rank * 64 + jl4;
    float4 bn4 = *reinterpret_cast<const float4*>(&bhh[d * GG + 2 * HH + jg4]);

    CLUSTER_SYNC_();

    unsigned smbase = (unsigned)__cvta_generic_to_shared(smem);
    unsigned ra0 = mapa_sh(smbase, 0);
    unsigned ra1 = mapa_sh(smbase, 1);
    unsigned ra2 = mapa_sh(smbase, 2);
    unsigned ra3 = mapa_sh(smbase, 3);

    int ar = lane >> 2;
    int aw = ar * 132 + (lane & 3);                  // A base word
    // B base word per gate (frag f = w), + kf*64 inside loop
    int bR = ((0 * 8 + w) * 16) * 64 + lane * 2;
    int bZ = ((1 * 8 + w) * 16) * 64 + lane * 2;
    int bN = ((2 * 8 + w) * 16) * 64 + lane * 2;

    // h-plane word offsets for phase-2 broadcast (4 consecutive j = 2 words)
    unsigned hw0 = (unsigned)(pb * 132 + (jg4 >> 1));

    float hn0 = 0.f, hn1 = 0.f, hn2 = 0.f, hn3 = 0.f;

    for (int s = 0; s < TT; s++) {
        int t = d ? (TT - 1 - s) : s;

        // early gi loads (consumed in phase 2)
        const float* gib = g_GI + ((size_t)d * (TT * BB) + (size_t)t * BB + b0 + pb) * GG;
        float4 gir = *reinterpret_cast<const float4*>(gib + jg4);
        float4 giz = *reinterpret_cast<const float4*>(gib + 256 + jg4);
        float4 gin = *reinterpret_cast<const float4*>(gib + 512 + jg4);

        // ---- phase 1: bf16x2 mma over k=256 (16 k16-frags) ----
        float accR[4] = {0.f, 0.f, 0.f, 0.f};
        float accZ[4] = {0.f, 0.f, 0.f, 0.f};
        float accN[4] = {0.f, 0.f, 0.f, 0.f};

#pragma unroll
        for (int kf = 0; kf < 16; kf++) {
            unsigned ahi[4], alo[4];
            ahi[0] = hhi[aw + kf * 8];
            ahi[1] = hhi[aw + kf * 8 + 1056];
            ahi[2] = hhi[aw + kf * 8 + 4];
            ahi[3] = hhi[aw + kf * 8 + 1060];
            alo[0] = hlo[aw + kf * 8];
            alo[1] = hlo[aw + kf * 8 + 1056];
            alo[2] = hlo[aw + kf * 8 + 4];
            alo[3] = hlo[aw + kf * 8 + 1060];

            uint2 bh, bl;
            bh = *reinterpret_cast<const uint2*>(&Wh[bR + kf * 64]);
            bl = *reinterpret_cast<const uint2*>(&Wl[bR + kf * 64]);
            mma_bf16(accR, ahi, bh.x, bh.y);
            mma_bf16(accR, ahi, bl.x, bl.y);
            mma_bf16(accR, alo, bh.x, bh.y);

            bh = *reinterpret_cast<const uint2*>(&Wh[bZ + kf * 64]);
            bl = *reinterpret_cast<const uint2*>(&Wl[bZ + kf * 64]);
            mma_bf16(accZ, ahi, bh.x, bh.y);
            mma_bf16(accZ, ahi, bl.x, bl.y);
            mma_bf16(accZ, alo, bh.x, bh.y);

            bh = *reinterpret_cast<const uint2*>(&Wh[bN + kf * 64]);
            bl = *reinterpret_cast<const uint2*>(&Wl[bN + kf * 64]);
            mma_bf16(accN, ahi, bh.x, bh.y);
            mma_bf16(accN, ahi, bl.x, bl.y);
            mma_bf16(accN, alo, bh.x, bh.y);
        }

        // stage accs via validated epilogue formula
#pragma unroll
        for (int i = 0; i < 4; i++) {
            int row = ar + ((i >> 1) ? 8 : 0);
            int col = w * 8 + (lane & 3) * 2 + (i & 1);
            stg[(0 * 16 + row) * WSTG + col] = accR[i];
            stg[(1 * 16 + row) * WSTG + col] = accZ[i];
            stg[(2 * 16 + row) * WSTG + col] = accN[i];
        }
        __syncthreads();

        // ---- phase 2: gating; hold = own registers ----
        float4 sR = *reinterpret_cast<const float4*>(&stg[(0 * 16 + pb) * WSTG + jl4]);
        float4 sZ = *reinterpret_cast<const float4*>(&stg[(1 * 16 + pb) * WSTG + jl4]);
        float4 sN = *reinterpret_cast<const float4*>(&stg[(2 * 16 + pb) * WSTG + jl4]);

        {
            float r, z, n;
            r = sigmoidf_fast(gir.x + sR.x);
            z = sigmoidf_fast(giz.x + sZ.x);
            n = tanhf(gin.x + r * (sN.x + bn4.x));
            hn0 = n + z * (hn0 - n);
            r = sigmoidf_fast(gir.y + sR.y);
            z = sigmoidf_fast(giz.y + sZ.y);
            n = tanhf(gin.y + r * (sN.y + bn4.y));
            hn1 = n + z * (hn1 - n);
            r = sigmoidf_fast(gir.z + sR.z);
            z = sigmoidf_fast(giz.z + sZ.z);
            n = tanhf(gin.z + r * (sN.z + bn4.z));
            hn2 = n + z * (hn2 - n);
            r = sigmoidf_fast(gir.w + sR.w);
            z = sigmoidf_fast(giz.w + sZ.w);
            n = tanhf(gin.w + r * (sN.w + bn4.w));
            hn3 = n + z * (hn3 - n);
        }

        // bf16 split + pack (2 words per plane)
        __nv_bfloat16 b0h = __float2bfloat16(hn0);
        __nv_bfloat16 b1h = __float2bfloat16(hn1);
        __nv_bfloat16 b2h = __float2bfloat16(hn2);
        __nv_bfloat16 b3h = __float2bfloat16(hn3);
        unsigned hiw0 = ((unsigned)__bfloat16_as_ushort(b1h) << 16) | __bfloat16_as_ushort(b0h);
        unsigned hiw1 = ((unsigned)__bfloat16_as_ushort(b3h) << 16) | __bfloat16_as_ushort(b2h);
        __nv_bfloat16 b0l = __float2bfloat16(hn0 - __bfloat162float(b0h));
        __nv_bfloat16 b1l = __float2bfloat16(hn1 - __bfloat162float(b1h));
        __nv_bfloat16 b2l = __float2bfloat16(hn2 - __bfloat162float(b2h));
        __nv_bfloat16 b3l = __float2bfloat16(hn3 - __bfloat162float(b3h));
        unsigned low0 = ((unsigned)__bfloat16_as_ushort(b1l) << 16) | __bfloat16_as_ushort(b0l);
        unsigned low1 = ((unsigned)__bfloat16_as_ushort(b3l) << 16) | __bfloat16_as_ushort(b2l);

        CLUSTER_SYNC_();   // all cluster phase-1 reads of h planes done

        unsigned ohi = AHI_OFF + hw0 * 4u;
        unsigned olo = ALO_OFF + hw0 * 4u;
#pragma unroll
        for (int rkt = 0; rkt < 4; rkt++) {
            unsigned base = (rkt == 0) ? ra0 : (rkt == 1) ? ra1 : (rkt == 2) ? ra2 : ra3;
            asm volatile("st.shared::cluster.b32 [%0], %1;" :: "r"(base + ohi),     "r"(hiw0) : "memory");
            asm volatile("st.shared::cluster.b32 [%0], %1;" :: "r"(base + ohi + 4), "r"(hiw1) : "memory");
            asm volatile("st.shared::cluster.b32 [%0], %1;" :: "r"(base + olo),     "r"(low0) : "memory");
            asm volatile("st.shared::cluster.b32 [%0], %1;" :: "r"(base + olo + 4), "r"(low1) : "memory");
        }

        if (layer == 0) {
            *reinterpret_cast<float4*>(
                &g_H1[((size_t)t * BB + b0 + pb) * (2 * HH) + (size_t)d * HH + jg4]) =
                make_float4(hn0, hn1, hn2, hn3);
        }

        CLUSTER_SYNC_();   // h_new visible everywhere
    }

    if (layer != 0) {
        *reinterpret_cast<float4*>(
            &fin[(size_t)(b0 + pb) * (2 * HH) + (size_t)d * HH + jg4]) =
            make_float4(hn0, hn1, hn2, hn3);
    }
}

// ---------------- launch ----------------
extern "C" void kernel_launch(void* const* d_in, const int* in_sizes, int n_in,
                              void* d_out, int out_size) {
    (void)in_sizes; (void)n_in; (void)out_size;
    const float* x     = (const float*)d_in[0];
    const float* w_ih0 = (const float*)d_in[1];
    const float* w_hh0 = (const float*)d_in[2];
    const float* b_ih0 = (const float*)d_in[3];
    const float* b_hh0 = (const float*)d_in[4];
    const float* w_ih1 = (const float*)d_in[5];
    const float* w_hh1 = (const float*)d_in[6];
    const float* b_ih1 = (const float*)d_in[7];
    const float* b_hh1 = (const float*)d_in[8];
    float* out = (float*)d_out;

    cudaFuncSetAttribute(gru_scan_mma, cudaFuncAttributeMaxDynamicSharedMemorySize, SMEM_SCAN);

    // order (harness prepends 2): transpose=2, prep=3, gemm0=4, scan0=5 <- ncu -s 5
    transpose_x<<<(BB * TT * (DD / 4) + 255) / 256, 256>>>(x);
    prep_wsplit<<<(16 * 24576 + 255) / 256, 256>>>(w_hh0, w_hh1);

    dim3 gg(512, 6, 2);
    gemm_tf32<<<gg, 256>>>(0, w_ih0, b_ih0, b_hh0);
    gru_scan_mma<<<128, 256, SMEM_SCAN>>>(0, b_hh0, nullptr);
    gemm_tf32<<<gg, 256>>>(1, w_ih1, b_ih1, b_hh1);
    gru_scan_mma<<<128, 256, SMEM_SCAN>>>(1, b_hh1, out);
}

// round 11
// speedup vs baseline: 1.7331x; 1.1187x over previous
#include <cuda_runtime.h>
#include <cuda_bf16.h>
#include <cstdint>

#define BB 256
#define TT 256
#define DD 64
#define HH 256
#define GG 768

// ---------------- scratch ----------------
__device__ float    g_XT[TT * BB * DD];
__device__ float    g_H1[TT * BB * 2 * HH];
__device__ float    g_GI[2 * TT * BB * GG];
__device__ unsigned g_Whi[16 * 24576];   // [l*2+d][rank] -> frag-ordered bf16x2 words (hi)
__device__ unsigned g_Wlo[16 * 24576];   // (lo)

// ---------------- helpers ----------------
__device__ __forceinline__ float sigmoidf_fast(float x) {
    return 1.0f / (1.0f + __expf(-x));
}
__device__ __forceinline__ unsigned cvt_tf32(float f) {
    unsigned r;
    asm volatile("cvt.rna.tf32.f32 %0, %1;" : "=r"(r) : "f"(f));
    return r;
}
__device__ __forceinline__ unsigned mapa_sh(unsigned addr, unsigned rnk) {
    unsigned ra;
    asm volatile("mapa.shared::cluster.u32 %0, %1, %2;" : "=r"(ra) : "r"(addr), "r"(rnk));
    return ra;
}
#define CLUSTER_SYNC_() \
    asm volatile("barrier.cluster.arrive.aligned;\n\tbarrier.cluster.wait.aligned;" ::: "memory")

__device__ __forceinline__ void mbar_init(unsigned addr, unsigned cnt) {
    asm volatile("mbarrier.init.shared.b64 [%0], %1;" :: "r"(addr), "r"(cnt) : "memory");
}
__device__ __forceinline__ void mbar_arrive_rank(unsigned remaddr) {
    asm volatile("mbarrier.arrive.shared::cluster.b64 _, [%0];" :: "r"(remaddr) : "memory");
}
__device__ __forceinline__ void mbar_wait_cluster(unsigned addr, unsigned parity) {
    unsigned done;
    do {
        asm volatile(
            "{\n\t.reg .pred p;\n\t"
            "mbarrier.try_wait.parity.acquire.cluster.shared::cta.b64 p, [%1], %2, 0x989680;\n\t"
            "selp.b32 %0, 1, 0, p;\n\t}"
            : "=r"(done) : "r"(addr), "r"(parity) : "memory");
    } while (!done);
}

__device__ __forceinline__ void mma_tf32(float* acc, const unsigned* a, unsigned b0, unsigned b1) {
    asm volatile(
        "mma.sync.aligned.m16n8k8.row.col.f32.tf32.tf32.f32 "
        "{%0,%1,%2,%3}, {%4,%5,%6,%7}, {%8,%9}, {%0,%1,%2,%3};\n"
        : "+f"(acc[0]), "+f"(acc[1]), "+f"(acc[2]), "+f"(acc[3])
        : "r"(a[0]), "r"(a[1]), "r"(a[2]), "r"(a[3]), "r"(b0), "r"(b1));
}
__device__ __forceinline__ void mma_bf16(float* acc, const unsigned* a, unsigned b0, unsigned b1) {
    asm volatile(
        "mma.sync.aligned.m16n8k16.row.col.f32.bf16.bf16.f32 "
        "{%0,%1,%2,%3}, {%4,%5,%6,%7}, {%8,%9}, {%0,%1,%2,%3};\n"
        : "+f"(acc[0]), "+f"(acc[1]), "+f"(acc[2]), "+f"(acc[3])
        : "r"(a[0]), "r"(a[1]), "r"(a[2]), "r"(a[3]), "r"(b0), "r"(b1));
}

// ---------------- transpose x ----------------
__global__ void transpose_x(const float* __restrict__ x) {
    int i = blockIdx.x * blockDim.x + threadIdx.x;
    if (i >= BB * TT * (DD / 4)) return;
    int d4 = i & 15;
    int t  = (i >> 4) & 255;
    int b  = i >> 12;
    const float4* src = reinterpret_cast<const float4*>(x);
    float4* dst = reinterpret_cast<float4*>(g_XT);
    dst[((t * BB + b) * (DD / 4)) + d4] = src[((b * TT + t) * (DD / 4)) + d4];
}

// ---------------- prep: split w_hh into fragment-ordered bf16 hi/lo planes ----------------
__global__ void prep_wsplit(const float* __restrict__ w0, const float* __restrict__ w1) {
    int i = blockIdx.x * blockDim.x + threadIdx.x;
    if (i >= 16 * 24576) return;
    int w64  = i & 63;
    int blk  = i >> 6;
    int kf   = blk & 15;
    int gfid = blk >> 4;
    int gf   = gfid % 24;
    int ldr  = gfid / 24;
    int rank = ldr & 3;
    int d    = (ldr >> 2) & 1;
    int l    = ldr >> 3;
    int g    = gf >> 3;
    int f    = gf & 7;
    int lane = w64 >> 1;
    int r    = w64 & 1;
    int row  = g * 256 + rank * 64 + f * 8 + (lane >> 2);
    int k    = kf * 16 + (lane & 3) * 2 + r * 8;
    const float* w = l ? w1 : w0;
    const float* p = w + ((size_t)d * GG + row) * HH + k;
    float v0 = p[0], v1 = p[1];
    __nv_bfloat16 h0 = __float2bfloat16(v0);
    __nv_bfloat16 h1 = __float2bfloat16(v1);
    __nv_bfloat16 l0 = __float2bfloat16(v0 - __bfloat162float(h0));
    __nv_bfloat16 l1 = __float2bfloat16(v1 - __bfloat162float(h1));
    g_Whi[i] = ((unsigned)__bfloat16_as_ushort(h1) << 16) | __bfloat16_as_ushort(h0);
    g_Wlo[i] = ((unsigned)__bfloat16_as_ushort(l1) << 16) | __bfloat16_as_ushort(l0);
}

// ---------------- gi GEMM: tf32x3, 128x128 tiles (validated, unchanged) ----------------
#define Bb_M 128
#define Bb_N 128
#define Bb_K 16
#define SSTR 20

__global__ void __launch_bounds__(256) gemm_tf32(int layer,
                                                 const float* __restrict__ Wih,
                                                 const float* __restrict__ bih,
                                                 const float* __restrict__ bhh) {
    __shared__ float sA[2][Bb_M * SSTR];
    __shared__ float sB[2][Bb_N * SSTR];

    const float* A = layer ? g_H1 : g_XT;
    const int K    = layer ? 512 : 64;
    float* C = g_GI;

    int tid  = threadIdx.x;
    int m0   = blockIdx.x * Bb_M;
    int n0   = blockIdx.y * Bb_N;
    int d    = blockIdx.z;
    const float* Ab = A + (size_t)m0 * K;
    const float* Wb = Wih + ((size_t)d * GG + n0) * K;
    float* Cb = C + (size_t)d * (TT * BB) * GG;

    int lane = tid & 31, wid = tid >> 5;
    int wm = wid & 3, wn = wid >> 2;

    float acc[2][8][4];
#pragma unroll
    for (int a = 0; a < 2; a++)
#pragma unroll
        for (int b = 0; b < 8; b++)
#pragma unroll
            for (int c = 0; c < 4; c++) acc[a][b][c] = 0.0f;

    auto load_tile = [&](int kt, int buf) {
        int k0 = kt * Bb_K;
#pragma unroll
        for (int i = 0; i < 2; i++) {
            int s   = tid * 2 + i;
            int row = s >> 2;
            int seg = s & 3;
            unsigned da = (unsigned)__cvta_generic_to_shared(&sA[buf][row * SSTR + seg * 4]);
            const float* ga = Ab + (size_t)row * K + k0 + seg * 4;
            asm volatile("cp.async.cg.shared.global [%0], [%1], 16;\n" :: "r"(da), "l"(ga));
            unsigned db = (unsigned)__cvta_generic_to_shared(&sB[buf][row * SSTR + seg * 4]);
            const float* gb = Wb + (size_t)row * K + k0 + seg * 4;
            asm volatile("cp.async.cg.shared.global [%0], [%1], 16;\n" :: "r"(db), "l"(gb));
        }
        asm volatile("cp.async.commit_group;\n" ::: "memory");
    };

    const int KT = K / Bb_K;
    load_tile(0, 0);
    for (int kt = 0; kt < KT; kt++) {
        int buf = kt & 1;
        if (kt + 1 < KT) {
            load_tile(kt + 1, buf ^ 1);
            asm volatile("cp.async.wait_group 1;\n" ::: "memory");
        } else {
            asm volatile("cp.async.wait_group 0;\n" ::: "memory");
        }
        __syncthreads();
        const float* a_s = sA[buf];
        const float* b_s = sB[buf];
#pragma unroll
        for (int ks = 0; ks < 2; ks++) {
            int kk = ks * 8;
            unsigned ahi[2][4], alo[2][4];
#pragma unroll
            for (int mf = 0; mf < 2; mf++) {
                const float* p = a_s + (wm * 32 + mf * 16 + (lane >> 2)) * SSTR + kk + (lane & 3);
                float f0 = p[0];
                float f1 = p[8 * SSTR];
                float f2 = p[4];
                float f3 = p[8 * SSTR + 4];
                ahi[mf][0] = cvt_tf32(f0); alo[mf][0] = __float_as_uint(f0 - __uint_as_float(ahi[mf][0]));
                ahi[mf][1] = cvt_tf32(f1); alo[mf][1] = __float_as_uint(f1 - __uint_as_float(ahi[mf][1]));
                ahi[mf][2] = cvt_tf32(f2); alo[mf][2] = __float_as_uint(f2 - __uint_as_float(ahi[mf][2]));
                ahi[mf][3] = cvt_tf32(f3); alo[mf][3] = __float_as_uint(f3 - __uint_as_float(ahi[mf][3]));
            }
#pragma unroll
            for (int nf = 0; nf < 8; nf++) {
                const float* p = b_s + (wn * 64 + nf * 8 + (lane >> 2)) * SSTR + kk + (lane & 3);
                float g0 = p[0];
                float g1 = p[4];
                unsigned bhi0 = cvt_tf32(g0), blo0 = __float_as_uint(g0 - __uint_as_float(bhi0));
                unsigned bhi1 = cvt_tf32(g1), blo1 = __float_as_uint(g1 - __uint_as_float(bhi1));
#pragma unroll
                for (int mf = 0; mf < 2; mf++) {
                    mma_tf32(acc[mf][nf], ahi[mf], bhi0, bhi1);
                    mma_tf32(acc[mf][nf], ahi[mf], blo0, blo1);
                    mma_tf32(acc[mf][nf], alo[mf], bhi0, bhi1);
                }
            }
        }
        __syncthreads();
    }

#pragma unroll
    for (int mf = 0; mf < 2; mf++)
#pragma unroll
        for (int nf = 0; nf < 8; nf++)
#pragma unroll
            for (int i = 0; i < 4; i++) {
                int row = m0 + wm * 32 + mf * 16 + (lane >> 2) + ((i >> 1) ? 8 : 0);
                int col = n0 + wn * 64 + nf * 8 + (lane & 3) * 2 + (i & 1);
                float bias = __ldg(&bih[d * GG + col]) +
                             (col < 2 * HH ? __ldg(&bhh[d * GG + col]) : 0.0f);
                Cb[(size_t)row * GG + col] = acc[mf][nf][i] + bias;
            }
}

// ---------------- GRU scan v6: bf16x2 mma + mbarrier sync (no barrier.cluster in loop) ----
#define WPL_W   24576
#define APL_W   (16 * 132)
#define WH_OFF  0
#define WL_OFF  (WPL_W * 4)                // 98304
#define AHI_OFF (2 * WPL_W * 4)            // 196608
#define ALO_OFF (AHI_OFF + APL_W * 4)      // 205056
#define STG_OFF (ALO_OFF + APL_W * 4)      // 213504
#define WSTG 68
#define MB_OFF  (STG_OFF + 3 * 16 * WSTG * 4)   // 226560; bar_reads @ +0, bar_writes @ +8
#define SMEM_SCAN (MB_OFF + 16)                 // 226576

__global__ void __launch_bounds__(256, 1) __cluster_dims__(4, 1, 1)
gru_scan_mma(int layer, const float* __restrict__ bhh, float* __restrict__ fin) {
    extern __shared__ char smem[];
    unsigned* Wh  = reinterpret_cast<unsigned*>(smem + WH_OFF);
    unsigned* Wl  = reinterpret_cast<unsigned*>(smem + WL_OFF);
    unsigned* hhi = reinterpret_cast<unsigned*>(smem + AHI_OFF);
    unsigned* hlo = reinterpret_cast<unsigned*>(smem + ALO_OFF);
    float*    stg = reinterpret_cast<float*>(smem + STG_OFF);

    int tid  = threadIdx.x;
    int lane = tid & 31;
    int w    = tid >> 5;
    int rank = blockIdx.x & 3;
    int cid  = blockIdx.x >> 2;
    int d    = cid & 1;
    int b0   = (cid >> 1) * 16;

    // load W planes
    {
        const uint4* shi = reinterpret_cast<const uint4*>(g_Whi + (size_t)((layer * 2 + d) * 4 + rank) * WPL_W);
        const uint4* slo = reinterpret_cast<const uint4*>(g_Wlo + (size_t)((layer * 2 + d) * 4 + rank) * WPL_W);
        uint4* dhi = reinterpret_cast<uint4*>(Wh);
        uint4* dlo = reinterpret_cast<uint4*>(Wl);
#pragma unroll 4
        for (int i = tid; i < WPL_W / 4; i += 256) { dhi[i] = shi[i]; dlo[i] = slo[i]; }
    }
    for (int i = tid; i < APL_W; i += 256) { hhi[i] = 0u; hlo[i] = 0u; }

    unsigned smbase = (unsigned)__cvta_generic_to_shared(smem);
    unsigned mb_reads_l  = smbase + MB_OFF;
    unsigned mb_writes_l = smbase + MB_OFF + 8;
    if (tid == 0) {
        mbar_init(mb_reads_l, 4);
        mbar_init(mb_writes_l, 4);
    }

    int pb  = tid >> 4;
    int jl4 = (tid & 15) * 4;
    int jg4 = rank * 64 + jl4;
    float4 bn4 = *reinterpret_cast<const float4*>(&bhh[d * GG + 2 * HH + jg4]);

    CLUSTER_SYNC_();   // once: smem init + mbarrier init visible cluster-wide

    unsigned ra0 = mapa_sh(smbase, 0);
    unsigned ra1 = mapa_sh(smbase, 1);
    unsigned ra2 = mapa_sh(smbase, 2);
    unsigned ra3 = mapa_sh(smbase, 3);

    // hoisted remote barrier addresses (tid0 only uses them, harmless elsewhere)
    unsigned rdb0 = ra0 + MB_OFF,     rdb1 = ra1 + MB_OFF,
             rdb2 = ra2 + MB_OFF,     rdb3 = ra3 + MB_OFF;
    unsigned wrb0 = ra0 + MB_OFF + 8, wrb1 = ra1 + MB_OFF + 8,
             wrb2 = ra2 + MB_OFF + 8, wrb3 = ra3 + MB_OFF + 8;

    int ar = lane >> 2;
    int aw = ar * 132 + (lane & 3);
    int bR = ((0 * 8 + w) * 16) * 64 + lane * 2;
    int bZ = ((1 * 8 + w) * 16) * 64 + lane * 2;
    int bN = ((2 * 8 + w) * 16) * 64 + lane * 2;

    unsigned hw0 = (unsigned)(pb * 132 + (jg4 >> 1));

    float hn0 = 0.f, hn1 = 0.f, hn2 = 0.f, hn3 = 0.f;

    for (int s = 0; s < TT; s++) {
        if (s) mbar_wait_cluster(mb_writes_l, (s & 1) ^ 1);   // h(s) visible everywhere

        int t = d ? (TT - 1 - s) : s;

        const float* gib = g_GI + ((size_t)d * (TT * BB) + (size_t)t * BB + b0 + pb) * GG;
        float4 gir = *reinterpret_cast<const float4*>(gib + jg4);
        float4 giz = *reinterpret_cast<const float4*>(gib + 256 + jg4);
        float4 gin = *reinterpret_cast<const float4*>(gib + 512 + jg4);

        // ---- phase 1: bf16x2 mma over k=256 ----
        float accR[4] = {0.f, 0.f, 0.f, 0.f};
        float accZ[4] = {0.f, 0.f, 0.f, 0.f};
        float accN[4] = {0.f, 0.f, 0.f, 0.f};

#pragma unroll
        for (int kf = 0; kf < 16; kf++) {
            unsigned ahi[4], alo[4];
            ahi[0] = hhi[aw + kf * 8];
            ahi[1] = hhi[aw + kf * 8 + 1056];
            ahi[2] = hhi[aw + kf * 8 + 4];
            ahi[3] = hhi[aw + kf * 8 + 1060];
            alo[0] = hlo[aw + kf * 8];
            alo[1] = hlo[aw + kf * 8 + 1056];
            alo[2] = hlo[aw + kf * 8 + 4];
            alo[3] = hlo[aw + kf * 8 + 1060];

            uint2 bh, bl;
            bh = *reinterpret_cast<const uint2*>(&Wh[bR + kf * 64]);
            bl = *reinterpret_cast<const uint2*>(&Wl[bR + kf * 64]);
            mma_bf16(accR, ahi, bh.x, bh.y);
            mma_bf16(accR, ahi, bl.x, bl.y);
            mma_bf16(accR, alo, bh.x, bh.y);

            bh = *reinterpret_cast<const uint2*>(&Wh[bZ + kf * 64]);
            bl = *reinterpret_cast<const uint2*>(&Wl[bZ + kf * 64]);
            mma_bf16(accZ, ahi, bh.x, bh.y);
            mma_bf16(accZ, ahi, bl.x, bl.y);
            mma_bf16(accZ, alo, bh.x, bh.y);

            bh = *reinterpret_cast<const uint2*>(&Wh[bN + kf * 64]);
            bl = *reinterpret_cast<const uint2*>(&Wl[bN + kf * 64]);
            mma_bf16(accN, ahi, bh.x, bh.y);
            mma_bf16(accN, ahi, bl.x, bl.y);
            mma_bf16(accN, alo, bh.x, bh.y);
        }

        // stage accs (validated epilogue formula)
#pragma unroll
        for (int i = 0; i < 4; i++) {
            int row = ar + ((i >> 1) ? 8 : 0);
            int col = w * 8 + (lane & 3) * 2 + (i & 1);
            stg[(0 * 16 + row) * WSTG + col] = accR[i];
            stg[(1 * 16 + row) * WSTG + col] = accZ[i];
            stg[(2 * 16 + row) * WSTG + col] = accN[i];
        }
        __syncthreads();   // staging visible + all h-plane reads in this CTA done

        // announce reads-done to all ranks (rendezvous only)
        if (tid == 0 && s + 1 < TT) {
            mbar_arrive_rank(rdb0);
            mbar_arrive_rank(rdb1);
            mbar_arrive_rank(rdb2);
            mbar_arrive_rank(rdb3);
        }

        // ---- phase 2: gating (hold = own registers) ----
        float4 sR = *reinterpret_cast<const float4*>(&stg[(0 * 16 + pb) * WSTG + jl4]);
        float4 sZ = *reinterpret_cast<const float4*>(&stg[(1 * 16 + pb) * WSTG + jl4]);
        float4 sN = *reinterpret_cast<const float4*>(&stg[(2 * 16 + pb) * WSTG + jl4]);

        {
            float r, z, n;
            r = sigmoidf_fast(gir.x + sR.x);
            z = sigmoidf_fast(giz.x + sZ.x);
            n = tanhf(gin.x + r * (sN.x + bn4.x));
            hn0 = n + z * (hn0 - n);
            r = sigmoidf_fast(gir.y + sR.y);
            z = sigmoidf_fast(giz.y + sZ.y);
            n = tanhf(gin.y + r * (sN.y + bn4.y));
            hn1 = n + z * (hn1 - n);
            r = sigmoidf_fast(gir.z + sR.z);
            z = sigmoidf_fast(giz.z + sZ.z);
            n = tanhf(gin.z + r * (sN.z + bn4.z));
            hn2 = n + z * (hn2 - n);
            r = sigmoidf_fast(gir.w + sR.w);
            z = sigmoidf_fast(giz.w + sZ.w);
            n = tanhf(gin.w + r * (sN.w + bn4.w));
            hn3 = n + z * (hn3 - n);
        }

        if (layer == 0) {
            *reinterpret_cast<float4*>(
                &g_H1[((size_t)t * BB + b0 + pb) * (2 * HH) + (size_t)d * HH + jg4]) =
                make_float4(hn0, hn1, hn2, hn3);
        }

        if (s + 1 < TT) {
            // bf16 split + pack
            __nv_bfloat16 b0h = __float2bfloat16(hn0);
            __nv_bfloat16 b1h = __float2bfloat16(hn1);
            __nv_bfloat16 b2h = __float2bfloat16(hn2);
            __nv_bfloat16 b3h = __float2bfloat16(hn3);
            unsigned hiw0 = ((unsigned)__bfloat16_as_ushort(b1h) << 16) | __bfloat16_as_ushort(b0h);
            unsigned hiw1 = ((unsigned)__bfloat16_as_ushort(b3h) << 16) | __bfloat16_as_ushort(b2h);
            __nv_bfloat16 b0l = __float2bfloat16(hn0 - __bfloat162float(b0h));
            __nv_bfloat16 b1l = __float2bfloat16(hn1 - __bfloat162float(b1h));
            __nv_bfloat16 b2l = __float2bfloat16(hn2 - __bfloat162float(b2h));
            __nv_bfloat16 b3l = __float2bfloat16(hn3 - __bfloat162float(b3h));
            unsigned low0 = ((unsigned)__bfloat16_as_ushort(b1l) << 16) | __bfloat16_as_ushort(b0l);
            unsigned low1 = ((unsigned)__bfloat16_as_ushort(b3l) << 16) | __bfloat16_as_ushort(b2l);

            mbar_wait_cluster(mb_reads_l, s & 1);   // every rank done reading h(s)

            unsigned ohi = AHI_OFF + hw0 * 4u;
            unsigned olo = ALO_OFF + hw0 * 4u;
#pragma unroll
            for (int rkt = 0; rkt < 4; rkt++) {
                unsigned base = (rkt == 0) ? ra0 : (rkt == 1) ? ra1 : (rkt == 2) ? ra2 : ra3;
                asm volatile("st.shared::cluster.b32 [%0], %1;" :: "r"(base + ohi),     "r"(hiw0) : "memory");
                asm volatile("st.shared::cluster.b32 [%0], %1;" :: "r"(base + ohi + 4), "r"(hiw1) : "memory");
                asm volatile("st.shared::cluster.b32 [%0], %1;" :: "r"(base + olo),     "r"(low0) : "memory");
                asm volatile("st.shared::cluster.b32 [%0], %1;" :: "r"(base + olo + 4), "r"(low1) : "memory");
            }

            __syncthreads();   // all threads' remote stores issued (happens-before tid0 fence)
            if (tid == 0) {
                asm volatile("fence.acq_rel.cluster;" ::: "memory");
                mbar_arrive_rank(wrb0);
                mbar_arrive_rank(wrb1);
                mbar_arrive_rank(wrb2);
                mbar_arrive_rank(wrb3);
            }
        }
    }

    if (layer != 0) {
        *reinterpret_cast<float4*>(
            &fin[(size_t)(b0 + pb) * (2 * HH) + (size_t)d * HH + jg4]) =
            make_float4(hn0, hn1, hn2, hn3);
    }

    CLUSTER_SYNC_();   // exit safety
}

// ---------------- launch ----------------
extern "C" void kernel_launch(void* const* d_in, const int* in_sizes, int n_in,
                              void* d_out, int out_size) {
    (void)in_sizes; (void)n_in; (void)out_size;
    const float* x     = (const float*)d_in[0];
    const float* w_ih0 = (const float*)d_in[1];
    const float* w_hh0 = (const float*)d_in[2];
    const float* b_ih0 = (const float*)d_in[3];
    const float* b_hh0 = (const float*)d_in[4];
    const float* w_ih1 = (const float*)d_in[5];
    const float* w_hh1 = (const float*)d_in[6];
    const float* b_ih1 = (const float*)d_in[7];
    const float* b_hh1 = (const float*)d_in[8];
    float* out = (float*)d_out;

    cudaFuncSetAttribute(gru_scan_mma, cudaFuncAttributeMaxDynamicSharedMemorySize, SMEM_SCAN);

    // order (harness prepends 2): transpose=2, prep=3, gemm0=4, scan0=5 <- ncu -s 5
    transpose_x<<<(BB * TT * (DD / 4) + 255) / 256, 256>>>(x);
    prep_wsplit<<<(16 * 24576 + 255) / 256, 256>>>(w_hh0, w_hh1);

    dim3 gg(512, 6, 2);
    gemm_tf32<<<gg, 256>>>(0, w_ih0, b_ih0, b_hh0);
    gru_scan_mma<<<128, 256, SMEM_SCAN>>>(0, b_hh0, nullptr);
    gemm_tf32<<<gg, 256>>>(1, w_ih1, b_ih1, b_hh1);
    gru_scan_mma<<<128, 256, SMEM_SCAN>>>(1, b_hh1, out);
}